// round 15
// baseline (speedup 1.0000x reference)
#include <cuda_runtime.h>

// ============================================================================
// Compile-time Wigner-3j machinery (mirrors the numpy reference exactly)
// ============================================================================
namespace ct {

constexpr double cfact(int n){ double r=1.0; for(int i=2;i<=n;i++) r *= (double)i; return r; }

constexpr double csqrt(double x){
  if (x <= 0.0) return 0.0;
  double g = x < 1.0 ? 1.0 : x;
  for (int i=0;i<200;i++) g = 0.5*(g + x/g);
  return g;
}

struct CD { double re; double im; };
constexpr CD cmul(CD a, CD b){ return CD{a.re*b.re - a.im*b.im, a.re*b.im + a.im*b.re}; }
constexpr CD cadd(CD a, CD b){ return CD{a.re+b.re, a.im+b.im}; }
constexpr CD cconj(CD a){ return CD{a.re, -a.im}; }
constexpr CD cscale(double s, CD a){ return CD{s*a.re, s*a.im}; }

constexpr void qfill(int l, CD q[11][11]){
  double s2 = 1.0/csqrt(2.0);
  for (int m=-l; m<0; ++m){ q[l+m][l-m] = CD{s2,0.0}; q[l+m][l+m] = CD{0.0,-s2}; }
  q[l][l] = CD{1.0,0.0};
  for (int m=1;m<=l;++m){
    double sg = (m&1)? -1.0 : 1.0;
    q[l+m][l+m] = CD{sg*s2,0.0}; q[l+m][l-m] = CD{0.0, sg*s2};
  }
  CD ph = (l%4==0)?CD{1,0} : (l%4==1)?CD{0,-1} : (l%4==2)?CD{-1,0} : CD{0,1};
  for (int a=0;a<2*l+1;a++) for (int b=0;b<2*l+1;b++) q[a][b] = cmul(q[a][b], ph);
}

struct W3 { float c[5][7][11]; };

constexpr W3 make_w3(int l1, int l2, int l3){
  double C[5][7][11] = {};
  for (int m1=-l1; m1<=l1; ++m1)
    for (int m2=-l2; m2<=l2; ++m2){
      int m3 = m1+m2;
      if (m3 < -l3 || m3 > l3) continue;
      double pref = csqrt((double)(2*l3+1)*cfact(l3+l1-l2)*cfact(l3-l1+l2)*cfact(l1+l2-l3)/cfact(l1+l2+l3+1));
      pref *= csqrt(cfact(l3+m3)*cfact(l3-m3)*cfact(l1-m1)*cfact(l1+m1)*cfact(l2-m2)*cfact(l2+m2));
      double s = 0.0;
      for (int k=0;k<=l1+l2-l3;k++){
        int dl0=k, dl1=l1+l2-l3-k, dl2=l1-m1-k, dl3=l2+m2-k, dl4=l3-l2+m1+k, dl5=l3-l1-m2+k;
        if (dl0<0||dl1<0||dl2<0||dl3<0||dl4<0||dl5<0) continue;
        double den = cfact(dl0)*cfact(dl1)*cfact(dl2)*cfact(dl3)*cfact(dl4)*cfact(dl5);
        s += ((k&1)? -1.0 : 1.0)/den;
      }
      C[l1+m1][l2+m2][l3+m3] = pref*s;
    }
  CD Q1[11][11]={}, Q2[11][11]={}, Q3[11][11]={};
  qfill(l1,Q1); qfill(l2,Q2); qfill(l3,Q3);
  const int d1=2*l1+1, d2=2*l2+1, d3=2*l3+1;
  CD T1[5][7][11]={};
  for (int j=0;j<d1;j++) for (int k=0;k<d2;k++) for (int m=0;m<d3;m++){
    CD s{0,0};
    for (int i=0;i<d1;i++) s = cadd(s, cscale(C[i][k][m], Q1[i][j]));
    T1[j][k][m]=s;
  }
  CD T2[5][7][11]={};
  for (int j=0;j<d1;j++) for (int l=0;l<d2;l++) for (int m=0;m<d3;m++){
    CD s{0,0};
    for (int k=0;k<d2;k++) s = cadd(s, cmul(Q2[k][l], T1[j][k][m]));
    T2[j][l][m]=s;
  }
  double R[5][7][11]={};
  double nrm2=0.0;
  for (int j=0;j<d1;j++) for (int l=0;l<d2;l++) for (int n=0;n<d3;n++){
    CD s{0,0};
    for (int m=0;m<d3;m++) s = cadd(s, cmul(cconj(Q3[n][m]), T2[j][l][m]));
    R[j][l][n]=s.re; nrm2 += s.re*s.re;
  }
  double nrm = csqrt(nrm2);
  double alpha = csqrt((double)(2*l3+1));
  W3 w{};
  for (int j=0;j<d1;j++) for (int l=0;l<d2;l++) for (int n=0;n<d3;n++){
    double vn = R[j][l][n]/nrm;
    if (vn < 1e-7 && vn > -1e-7) vn = 0.0;
    w.c[j][l][n] = (float)(vn*alpha);
  }
  return w;
}

} // namespace ct

// ============================================================================
// Compile-time path enumeration + e3nn output ordering
// ============================================================================
struct PInfo { int i1,i2,l1,l2,l3,p3; };
struct PathSet { PInfo p[28]; int order[28]; int chunk_off[28]; int npaths; };

constexpr PathSet make_paths(){
  PathSet R{};
  const int L1[3]={0,1,2}; const int P1[3]={1,-1,1};
  const int L2[4]={0,1,2,3}; const int P2[4]={1,-1,1,-1};
  int n=0;
  for (int i1=0;i1<3;i1++) for (int i2=0;i2<4;i2++){
    int lo = L1[i1]-L2[i2]; if (lo<0) lo=-lo;
    for (int l3=lo; l3<=L1[i1]+L2[i2]; l3++){
      R.p[n] = PInfo{i1,i2,L1[i1],L2[i2],l3, P1[i1]*P2[i2]};
      n++;
    }
  }
  R.npaths = n;
  for (int i=0;i<28;i++) R.order[i]=i;
  for (int i=1;i<28;i++){
    int v = R.order[i];
    int vl = R.p[v].l3;
    int v2 = -R.p[v].p3 * ((vl%2==0)?1:-1);
    int kv = vl*4 + (v2+1);
    int j=i-1;
    while (j>=0){
      int o=R.order[j]; int ol=R.p[o].l3; int o2=-R.p[o].p3*((ol%2==0)?1:-1); int ko=ol*4+(o2+1);
      if (ko>kv){ R.order[j+1]=R.order[j]; j--; } else break;
    }
    R.order[j+1]=v;
  }
  int off=0;
  for (int t=0;t<28;t++){ R.chunk_off[t]=off; off += 64*(2*R.p[R.order[t]].l3+1); }
  return R;
}
constexpr PathSet PT = make_paths();
static_assert(PT.npaths==28, "path count");
static_assert(PT.chunk_off[27] + 64*(2*PT.p[PT.order[27]].l3+1) == 9216, "out dim");

template<int P> struct W3Of { static constexpr ct::W3 v = ct::make_w3(PT.p[P].l1, PT.p[P].l2, PT.p[P].l3); };

template<int P, int I, int J, int K>
inline constexpr float CW = W3Of<P>::v.c[I][J][K];

// ============================================================================
// Split the 28 ordered chunks into four cost-balanced contiguous quarters
// ============================================================================
constexpr int NSIDE = 4;

constexpr int coff_end(int t){ return (t >= 28) ? 9216 : PT.chunk_off[t]; }

constexpr int pick_split_at(int target, int lo){
  int best=lo, bestd=1<<30;
  for (int S=lo; S<28; S++){
    int sz = PT.chunk_off[S];
    int d = (sz>target)? (sz-target) : (target-sz);
    if (d<bestd){ bestd=d; best=S; }
  }
  return best;
}
constexpr int SPL1 = pick_split_at(2304, 1);
constexpr int SPL2 = pick_split_at(4608, SPL1+1);
constexpr int SPL3 = pick_split_at(6912, SPL2+1);

constexpr int split_lo(int s){ return (s==0)?0 : (s==1)?SPL1 : (s==2)?SPL2 : SPL3; }
constexpr int split_hi(int s){ return (s==0)?SPL1 : (s==1)?SPL2 : (s==2)?SPL3 : 28; }

constexpr int hoff_host(int s){ return coff_end(split_lo(s)); }
constexpr int hlen_host(int s){ return coff_end(split_hi(s)) - coff_end(split_lo(s)); }

constexpr int hmax_host(){
  int m=0; for (int s=0;s<NSIDE;s++){ int l=hlen_host(s); if (l>m) m=l; }
  return m;
}
constexpr int HMAX = hmax_host();

template<int S> inline constexpr int HOFFV = hoff_host(S);
template<int S> inline constexpr int HLENV = hlen_host(S);

// ============================================================================
// Per-side group tables: chunks grouped by (i1,i2) within each side
// ============================================================================
struct GroupTab { int nt[12]; int T[12][5]; };
constexpr GroupTab make_groups_side(int side){
  GroupTab G{};
  for (int g=0; g<12; g++){ G.nt[g]=0; for (int c=0;c<5;c++) G.T[g][c]=-1; }
  for (int t=split_lo(side); t<split_hi(side); t++){
    int p = PT.order[t];
    int g = PT.p[p].i1*4 + PT.p[p].i2;
    G.T[g][G.nt[g]] = t; G.nt[g]++;
  }
  return G;
}
constexpr GroupTab GTS[NSIDE] = { make_groups_side(0), make_groups_side(1),
                                  make_groups_side(2), make_groups_side(3) };

constexpr int acc_off_host(int side, int g, int c){
  int s=0;
  for (int cc=0; cc<c; cc++){ int p = PT.order[GTS[side].T[g][cc]]; s += 2*PT.p[p].l3+1; }
  return s;
}

template<int S, int G, int C> inline constexpr int ACCOFF = acc_off_host(S, G, C);
template<int S, int G, int C> inline constexpr int GTT   = GTS[S].T[G][C];
template<int T>               inline constexpr int PTH   = PT.order[T];
template<int T>               inline constexpr int D3T   = 2*PT.p[PT.order[T]].l3+1;
template<int T>               inline constexpr int COFF  = PT.chunk_off[T];

// ============================================================================
// Per-side task lists: greedy chunk packing with accumulator cap (<=10 floats)
// ============================================================================
struct TaskDef { int g; int c0; int c1; };
struct TaskList { TaskDef td[24]; int n; };
constexpr TaskList make_tasklist(int side){
  TaskList L{}; L.n = 0;
  for (int g=0; g<12; g++){
    int nt = GTS[side].nt[g];
    int c0 = 0;
    while (c0 < nt){
      int c1 = c0, sum = 0;
      while (c1 < nt){
        int p = PT.order[GTS[side].T[g][c1]];
        int d3 = 2*PT.p[p].l3+1;
        if (sum + d3 > 10 && c1 > c0) break;
        sum += d3; c1++;
      }
      L.td[L.n] = TaskDef{g,c0,c1}; L.n++;
      c0 = c1;
    }
  }
  return L;
}
constexpr TaskList TLS[NSIDE] = { make_tasklist(0), make_tasklist(1),
                                  make_tasklist(2), make_tasklist(3) };

constexpr int task_cost(int side, int i){
  TaskDef t = TLS[side].td[i];
  int d1 = 2*(t.g/4)+1, d2 = 2*(t.g%4)+1;
  int s = d1 + d2 + 10;
  for (int c=t.c0; c<t.c1; c++){
    int p = PT.order[GTS[side].T[t.g][c]];
    int d3 = 2*PT.p[p].l3+1;
    s += d1*d2*(d3+3)/2 + d3;
  }
  return s;
}

// ============================================================================
// Compile-time LPT schedule per side: (task, half) units -> 8 warps
// ============================================================================
constexpr int NWARP = 8;
constexpr int MAXS  = 8;
struct Sched { int t[NWARP][MAXS]; int n[NWARP]; };

constexpr Sched make_sched(int side){
  Sched S{};
  for (int w=0;w<NWARP;w++){ S.n[w]=0; for (int s=0;s<MAXS;s++) S.t[w][s]=-1; }
  int nunit = TLS[side].n * 2;
  int ids[48] = {}; int ct_[48] = {};
  for (int i=0;i<nunit;i++){ ids[i]=i; ct_[i]=task_cost(side, i>>1); }
  for (int i=1;i<nunit;i++){
    int v=ids[i]; int j=i-1;
    while (j>=0 && ct_[ids[j]] < ct_[v]){ ids[j+1]=ids[j]; j--; }
    ids[j+1]=v;
  }
  int load[NWARP]={};
  for (int i=0;i<nunit;i++){
    int best=0; for (int w=1;w<NWARP;w++) if (load[w]<load[best]) best=w;
    S.t[best][S.n[best]] = ids[i]; S.n[best]+=1; load[best]+=ct_[ids[i]];
  }
  return S;
}
constexpr Sched SCHEDS[NSIDE] = { make_sched(0), make_sched(1), make_sched(2), make_sched(3) };
constexpr bool sched_ok(){
  for (int s=0;s<NSIDE;s++) for (int w=0;w<NWARP;w++) if (SCHEDS[s].n[w]>MAXS) return false;
  return true;
}
static_assert(sched_ok(), "schedule overflow");

// ============================================================================
// Device kernel
// ============================================================================
template<int I> struct Ic { static constexpr int value = I; };

template<int N, class F> __device__ __forceinline__ void cfor(F f){
  if constexpr (N > 0){ cfor<N-1, F>(f); f(Ic<N-1>{}); }
}

__device__ __forceinline__ unsigned smem_u32(const void* p){
  unsigned a;
  asm("{ .reg .u64 t; cvta.to.shared.u64 t, %1; cvt.u32.u64 %0, t; }" : "=r"(a) : "l"(p));
  return a;
}

// One (side SIDE, task TI, u-half H). Inputs straight from global (L1-resident).
template<int SIDE, int TI, int H>
__device__ __forceinline__ void do_group(int lane, float* __restrict__ so,
                                         const float* __restrict__ xr, const float* __restrict__ yr){
  constexpr int G  = TLS[SIDE].td[TI].g;
  constexpr int C0 = TLS[SIDE].td[TI].c0;
  constexpr int C1 = TLS[SIDE].td[TI].c1;
  constexpr int i1 = G/4, i2 = G%4;
  constexpr int d1 = 2*i1+1, d2 = 2*i2+1;
  constexpr int xb = (i1==0)?0 : (i1==1)?64 : 256;
  constexpr int yb = (i2==0)?0 : (i2==1)?1 : (i2==2)?4 : 9;
  constexpr int A0 = ACCOFF<SIDE,G,C0>;
  constexpr int NA = ACCOFF<SIDE,G,C1> - A0;

  const int u = H*32 + lane;

  float xv[d1], yv[d2], acc[NA];
  cfor<d1>([&](auto I){ constexpr int iv = decltype(I)::value;
                        xv[iv] = __ldg(xr + xb + u*d1 + iv); });
  cfor<d2>([&](auto J){ constexpr int jv = decltype(J)::value;
                        yv[jv] = __ldg(yr + yb + jv); });
  cfor<NA>([&](auto K){ acc[decltype(K)::value] = 0.0f; });

  cfor<d2>([&](auto J){
    cfor<d1>([&](auto I){
      constexpr int iv = decltype(I)::value, jv = decltype(J)::value;
      float pr = xv[iv]*yv[jv];   // shared across this task's l3 chunks
      cfor<C1-C0>([&](auto C){
        constexpr int cc = C0 + decltype(C)::value;
        constexpr int T  = GTT<SIDE, G, cc>;
        constexpr int p  = PTH<T>;
        constexpr int d3 = D3T<T>;
        constexpr int ao = ACCOFF<SIDE, G, cc> - A0;
        cfor<d3>([&](auto K){
          constexpr int kv = decltype(K)::value;
          constexpr float c = CW<p, iv, jv, kv>;
          if constexpr (c != 0.0f) acc[ao+kv] = fmaf(c, pr, acc[ao+kv]);  // FFMA-imm
        });
      });
    });
  });

  cfor<C1-C0>([&](auto C){
    constexpr int cc = C0 + decltype(C)::value;
    constexpr int T  = GTT<SIDE, G, cc>;
    constexpr int d3 = D3T<T>;
    constexpr int off= COFF<T> - HOFFV<SIDE>;   // side-local offset (compile-time)
    constexpr int ao = ACCOFF<SIDE, G, cc> - A0;
    cfor<d3>([&](auto K){ constexpr int kv = decltype(K)::value;
                          so[off + u*d3 + kv] = acc[ao+kv]; });      // odd stride -> conflict-free
  });
}

template<int SIDE, int W>
__device__ __forceinline__ void run_warp(int lane, float* __restrict__ so,
                                         const float* __restrict__ xr, const float* __restrict__ yr){
  cfor<MAXS>([&](auto S){
    constexpr int tk = SCHEDS[SIDE].t[W][decltype(S)::value];
    if constexpr (tk >= 0) do_group<SIDE,(tk>>1),(tk&1)>(lane, so, xr, yr);
  });
}

constexpr int ROWS = 4;   // batch rows per block

// One quarter-row: wait for buffer, compute, fence, issue bulk store.
template<int SIDE>
__device__ __forceinline__ void do_side(int tid, int w, int lane, int iter,
                                        float* __restrict__ sob,
                                        const float* __restrict__ xr, const float* __restrict__ yr,
                                        float* __restrict__ og){
  if (tid == 0 && iter >= 2)
    asm volatile("cp.async.bulk.wait_group.read 1;" ::: "memory");
  __syncthreads();
  switch (w){
    case 0: run_warp<SIDE,0>(lane, sob, xr, yr); break;
    case 1: run_warp<SIDE,1>(lane, sob, xr, yr); break;
    case 2: run_warp<SIDE,2>(lane, sob, xr, yr); break;
    case 3: run_warp<SIDE,3>(lane, sob, xr, yr); break;
    case 4: run_warp<SIDE,4>(lane, sob, xr, yr); break;
    case 5: run_warp<SIDE,5>(lane, sob, xr, yr); break;
    case 6: run_warp<SIDE,6>(lane, sob, xr, yr); break;
    case 7: run_warp<SIDE,7>(lane, sob, xr, yr); break;
  }
  asm volatile("fence.proxy.async.shared::cta;" ::: "memory");
  __syncthreads();
  if (tid == 0){
    unsigned sa = smem_u32(sob);
    asm volatile("cp.async.bulk.global.shared::cta.bulk_group [%0], [%1], %2;"
                 :: "l"(og + HOFFV<SIDE>), "r"(sa), "r"((unsigned)(HLENV<SIDE>*4)) : "memory");
    asm volatile("cp.async.bulk.commit_group;" ::: "memory");
  }
}

__global__ void __launch_bounds__(256, 8)
tp_kernel(const float* __restrict__ x, const float* __restrict__ y, float* __restrict__ out, int B){
  __shared__ __align__(16) float so[2][HMAX];   // quarter-row double buffer (~18.5 KB)

  const int base = blockIdx.x * ROWS;
  const int tid = threadIdx.x;
  const int w = tid >> 5, lane = tid & 31;

  int iter = 0;
  #pragma unroll 1
  for (int r = 0; r < ROWS; r++){
    const int b = base + r;
    if (b >= B) break;
    const float* xr = x + (long)b*576;
    const float* yr = y + (long)b*16;
    float* og = out + (long)b*9216;

    do_side<0>(tid, w, lane, iter, so[iter & 1], xr, yr, og); iter++;
    do_side<1>(tid, w, lane, iter, so[iter & 1], xr, yr, og); iter++;
    do_side<2>(tid, w, lane, iter, so[iter & 1], xr, yr, og); iter++;
    do_side<3>(tid, w, lane, iter, so[iter & 1], xr, yr, og); iter++;
  }

  // drain outstanding bulk stores before the CTA exits (smem dealloc)
  if (tid == 0)
    asm volatile("cp.async.bulk.wait_group.read 0;" ::: "memory");
  __syncthreads();
}

// ============================================================================
// Launch
// ============================================================================
extern "C" void kernel_launch(void* const* d_in, const int* in_sizes, int n_in,
                              void* d_out, int out_size) {
  const float* x = (const float*)d_in[0];
  const float* y = (const float*)d_in[1];
  float* out = (float*)d_out;
  const int B = in_sizes[0] / 576;
  if (B <= 0) return;
  const int blocks = (B + ROWS - 1) / ROWS;
  tp_kernel<<<blocks, 256>>>(x, y, out, B);
}

// round 16
// speedup vs baseline: 1.0524x; 1.0524x over previous
#include <cuda_runtime.h>

// ============================================================================
// Compile-time Wigner-3j machinery (mirrors the numpy reference exactly)
// ============================================================================
namespace ct {

constexpr double cfact(int n){ double r=1.0; for(int i=2;i<=n;i++) r *= (double)i; return r; }

constexpr double csqrt(double x){
  if (x <= 0.0) return 0.0;
  double g = x < 1.0 ? 1.0 : x;
  for (int i=0;i<200;i++) g = 0.5*(g + x/g);
  return g;
}

struct CD { double re; double im; };
constexpr CD cmul(CD a, CD b){ return CD{a.re*b.re - a.im*b.im, a.re*b.im + a.im*b.re}; }
constexpr CD cadd(CD a, CD b){ return CD{a.re+b.re, a.im+b.im}; }
constexpr CD cconj(CD a){ return CD{a.re, -a.im}; }
constexpr CD cscale(double s, CD a){ return CD{s*a.re, s*a.im}; }

constexpr void qfill(int l, CD q[11][11]){
  double s2 = 1.0/csqrt(2.0);
  for (int m=-l; m<0; ++m){ q[l+m][l-m] = CD{s2,0.0}; q[l+m][l+m] = CD{0.0,-s2}; }
  q[l][l] = CD{1.0,0.0};
  for (int m=1;m<=l;++m){
    double sg = (m&1)? -1.0 : 1.0;
    q[l+m][l+m] = CD{sg*s2,0.0}; q[l+m][l-m] = CD{0.0, sg*s2};
  }
  CD ph = (l%4==0)?CD{1,0} : (l%4==1)?CD{0,-1} : (l%4==2)?CD{-1,0} : CD{0,1};
  for (int a=0;a<2*l+1;a++) for (int b=0;b<2*l+1;b++) q[a][b] = cmul(q[a][b], ph);
}

struct W3 { float c[5][7][11]; };

constexpr W3 make_w3(int l1, int l2, int l3){
  double C[5][7][11] = {};
  for (int m1=-l1; m1<=l1; ++m1)
    for (int m2=-l2; m2<=l2; ++m2){
      int m3 = m1+m2;
      if (m3 < -l3 || m3 > l3) continue;
      double pref = csqrt((double)(2*l3+1)*cfact(l3+l1-l2)*cfact(l3-l1+l2)*cfact(l1+l2-l3)/cfact(l1+l2+l3+1));
      pref *= csqrt(cfact(l3+m3)*cfact(l3-m3)*cfact(l1-m1)*cfact(l1+m1)*cfact(l2-m2)*cfact(l2+m2));
      double s = 0.0;
      for (int k=0;k<=l1+l2-l3;k++){
        int dl0=k, dl1=l1+l2-l3-k, dl2=l1-m1-k, dl3=l2+m2-k, dl4=l3-l2+m1+k, dl5=l3-l1-m2+k;
        if (dl0<0||dl1<0||dl2<0||dl3<0||dl4<0||dl5<0) continue;
        double den = cfact(dl0)*cfact(dl1)*cfact(dl2)*cfact(dl3)*cfact(dl4)*cfact(dl5);
        s += ((k&1)? -1.0 : 1.0)/den;
      }
      C[l1+m1][l2+m2][l3+m3] = pref*s;
    }
  CD Q1[11][11]={}, Q2[11][11]={}, Q3[11][11]={};
  qfill(l1,Q1); qfill(l2,Q2); qfill(l3,Q3);
  const int d1=2*l1+1, d2=2*l2+1, d3=2*l3+1;
  CD T1[5][7][11]={};
  for (int j=0;j<d1;j++) for (int k=0;k<d2;k++) for (int m=0;m<d3;m++){
    CD s{0,0};
    for (int i=0;i<d1;i++) s = cadd(s, cscale(C[i][k][m], Q1[i][j]));
    T1[j][k][m]=s;
  }
  CD T2[5][7][11]={};
  for (int j=0;j<d1;j++) for (int l=0;l<d2;l++) for (int m=0;m<d3;m++){
    CD s{0,0};
    for (int k=0;k<d2;k++) s = cadd(s, cmul(Q2[k][l], T1[j][k][m]));
    T2[j][l][m]=s;
  }
  double R[5][7][11]={};
  double nrm2=0.0;
  for (int j=0;j<d1;j++) for (int l=0;l<d2;l++) for (int n=0;n<d3;n++){
    CD s{0,0};
    for (int m=0;m<d3;m++) s = cadd(s, cmul(cconj(Q3[n][m]), T2[j][l][m]));
    R[j][l][n]=s.re; nrm2 += s.re*s.re;
  }
  double nrm = csqrt(nrm2);
  double alpha = csqrt((double)(2*l3+1));
  W3 w{};
  for (int j=0;j<d1;j++) for (int l=0;l<d2;l++) for (int n=0;n<d3;n++){
    double vn = R[j][l][n]/nrm;
    if (vn < 1e-7 && vn > -1e-7) vn = 0.0;
    w.c[j][l][n] = (float)(vn*alpha);
  }
  return w;
}

} // namespace ct

// ============================================================================
// Compile-time path enumeration + e3nn output ordering
// ============================================================================
struct PInfo { int i1,i2,l1,l2,l3,p3; };
struct PathSet { PInfo p[28]; int order[28]; int chunk_off[28]; int npaths; };

constexpr PathSet make_paths(){
  PathSet R{};
  const int L1[3]={0,1,2}; const int P1[3]={1,-1,1};
  const int L2[4]={0,1,2,3}; const int P2[4]={1,-1,1,-1};
  int n=0;
  for (int i1=0;i1<3;i1++) for (int i2=0;i2<4;i2++){
    int lo = L1[i1]-L2[i2]; if (lo<0) lo=-lo;
    for (int l3=lo; l3<=L1[i1]+L2[i2]; l3++){
      R.p[n] = PInfo{i1,i2,L1[i1],L2[i2],l3, P1[i1]*P2[i2]};
      n++;
    }
  }
  R.npaths = n;
  for (int i=0;i<28;i++) R.order[i]=i;
  for (int i=1;i<28;i++){
    int v = R.order[i];
    int vl = R.p[v].l3;
    int v2 = -R.p[v].p3 * ((vl%2==0)?1:-1);
    int kv = vl*4 + (v2+1);
    int j=i-1;
    while (j>=0){
      int o=R.order[j]; int ol=R.p[o].l3; int o2=-R.p[o].p3*((ol%2==0)?1:-1); int ko=ol*4+(o2+1);
      if (ko>kv){ R.order[j+1]=R.order[j]; j--; } else break;
    }
    R.order[j+1]=v;
  }
  int off=0;
  for (int t=0;t<28;t++){ R.chunk_off[t]=off; off += 64*(2*R.p[R.order[t]].l3+1); }
  return R;
}
constexpr PathSet PT = make_paths();
static_assert(PT.npaths==28, "path count");
static_assert(PT.chunk_off[27] + 64*(2*PT.p[PT.order[27]].l3+1) == 9216, "out dim");

template<int P> struct W3Of { static constexpr ct::W3 v = ct::make_w3(PT.p[P].l1, PT.p[P].l2, PT.p[P].l3); };

template<int P, int I, int J, int K>
inline constexpr float CW = W3Of<P>::v.c[I][J][K];

// ============================================================================
// Size-balanced split of the 28 ordered chunks into two contiguous halves
// ============================================================================
constexpr int pick_split(){
  int best=1, bestd=1<<30;
  for (int S=1;S<28;S++){
    int sz = PT.chunk_off[S];
    int d = (sz>4608)? (sz-4608) : (4608-sz);
    if (d<bestd){ bestd=d; best=S; }
  }
  return best;
}
constexpr int SPLITC = pick_split();
constexpr int HOFF0 = 0;
constexpr int HOFF1 = PT.chunk_off[SPLITC];
constexpr int HLEN0 = PT.chunk_off[SPLITC];
constexpr int HLEN1 = 9216 - PT.chunk_off[SPLITC];
constexpr int HMAX  = (HLEN0 > HLEN1) ? HLEN0 : HLEN1;

template<int S> inline constexpr int HOFFV = S ? HOFF1 : HOFF0;

// ============================================================================
// Per-side group tables: chunks grouped by (i1,i2) within each side
// ============================================================================
struct GroupTab { int nt[12]; int T[12][5]; };
constexpr GroupTab make_groups_side(int side){
  GroupTab G{};
  for (int g=0; g<12; g++){ G.nt[g]=0; for (int c=0;c<5;c++) G.T[g][c]=-1; }
  for (int t=0;t<28;t++){
    int s = (t < SPLITC) ? 0 : 1;
    if (s != side) continue;
    int p = PT.order[t];
    int g = PT.p[p].i1*4 + PT.p[p].i2;
    G.T[g][G.nt[g]] = t; G.nt[g]++;
  }
  return G;
}
constexpr GroupTab GTS[2] = { make_groups_side(0), make_groups_side(1) };

constexpr int acc_off_host(int side, int g, int c){
  int s=0;
  for (int cc=0; cc<c; cc++){ int p = PT.order[GTS[side].T[g][cc]]; s += 2*PT.p[p].l3+1; }
  return s;
}

template<int S, int G, int C> inline constexpr int ACCOFF = acc_off_host(S, G, C);
template<int S, int G, int C> inline constexpr int GTT   = GTS[S].T[G][C];
template<int T>               inline constexpr int PTH   = PT.order[T];
template<int T>               inline constexpr int D3T   = 2*PT.p[PT.order[T]].l3+1;
template<int T>               inline constexpr int COFF  = PT.chunk_off[T];

// ============================================================================
// Per-side task lists: greedy chunk packing with accumulator cap (<=14 floats)
// ============================================================================
struct TaskDef { int g; int c0; int c1; };
struct TaskList { TaskDef td[24]; int n; };
constexpr TaskList make_tasklist(int side){
  TaskList L{}; L.n = 0;
  for (int g=0; g<12; g++){
    int nt = GTS[side].nt[g];
    int c0 = 0;
    while (c0 < nt){
      int c1 = c0, sum = 0;
      while (c1 < nt){
        int p = PT.order[GTS[side].T[g][c1]];
        int d3 = 2*PT.p[p].l3+1;
        if (sum + d3 > 14 && c1 > c0) break;
        sum += d3; c1++;
      }
      L.td[L.n] = TaskDef{g,c0,c1}; L.n++;
      c0 = c1;
    }
  }
  return L;
}
constexpr TaskList TLS[2] = { make_tasklist(0), make_tasklist(1) };

constexpr int task_cost(int side, int i){
  TaskDef t = TLS[side].td[i];
  int d1 = 2*(t.g/4)+1, d2 = 2*(t.g%4)+1;
  int s = d1 + d2 + 10;
  for (int c=t.c0; c<t.c1; c++){
    int p = PT.order[GTS[side].T[t.g][c]];
    int d3 = 2*PT.p[p].l3+1;
    s += d1*d2*(d3+3)/2 + d3;
  }
  return s;
}

// ============================================================================
// Compile-time LPT schedule per side: (task, half) units -> 8 warps
// ============================================================================
constexpr int NWARP = 8;
constexpr int MAXS  = 8;
struct Sched { int t[NWARP][MAXS]; int n[NWARP]; };

constexpr Sched make_sched(int side){
  Sched S{};
  for (int w=0;w<NWARP;w++){ S.n[w]=0; for (int s=0;s<MAXS;s++) S.t[w][s]=-1; }
  int nunit = TLS[side].n * 2;
  int ids[48] = {}; int ct_[48] = {};
  for (int i=0;i<nunit;i++){ ids[i]=i; ct_[i]=task_cost(side, i>>1); }
  for (int i=1;i<nunit;i++){
    int v=ids[i]; int j=i-1;
    while (j>=0 && ct_[ids[j]] < ct_[v]){ ids[j+1]=ids[j]; j--; }
    ids[j+1]=v;
  }
  int load[NWARP]={};
  for (int i=0;i<nunit;i++){
    int best=0; for (int w=1;w<NWARP;w++) if (load[w]<load[best]) best=w;
    S.t[best][S.n[best]] = ids[i]; S.n[best]+=1; load[best]+=ct_[ids[i]];
  }
  return S;
}
constexpr Sched SCHEDS[2] = { make_sched(0), make_sched(1) };
constexpr bool sched_ok(){
  for (int s=0;s<2;s++) for (int w=0;w<NWARP;w++) if (SCHEDS[s].n[w]>MAXS) return false;
  return true;
}
static_assert(sched_ok(), "schedule overflow");

// ============================================================================
// Device kernel
// ============================================================================
template<int I> struct Ic { static constexpr int value = I; };

template<int N, class F> __device__ __forceinline__ void cfor(F f){
  if constexpr (N > 0){ cfor<N-1, F>(f); f(Ic<N-1>{}); }
}

__device__ __forceinline__ unsigned smem_u32(const void* p){
  unsigned a;
  asm("{ .reg .u64 t; cvta.to.shared.u64 t, %1; cvt.u32.u64 %0, t; }" : "=r"(a) : "l"(p));
  return a;
}

// One (side SIDE, task TI, u-half H). Inputs straight from global (L1-resident).
// Output lands in the side-local staging buffer.
template<int SIDE, int TI, int H>
__device__ __forceinline__ void do_group(int lane, float* __restrict__ so,
                                         const float* __restrict__ xr, const float* __restrict__ yr){
  constexpr int G  = TLS[SIDE].td[TI].g;
  constexpr int C0 = TLS[SIDE].td[TI].c0;
  constexpr int C1 = TLS[SIDE].td[TI].c1;
  constexpr int i1 = G/4, i2 = G%4;
  constexpr int d1 = 2*i1+1, d2 = 2*i2+1;
  constexpr int xb = (i1==0)?0 : (i1==1)?64 : 256;
  constexpr int yb = (i2==0)?0 : (i2==1)?1 : (i2==2)?4 : 9;
  constexpr int A0 = ACCOFF<SIDE,G,C0>;
  constexpr int NA = ACCOFF<SIDE,G,C1> - A0;

  const int u = H*32 + lane;

  float xv[d1], yv[d2], acc[NA];
  cfor<d1>([&](auto I){ constexpr int iv = decltype(I)::value;
                        xv[iv] = __ldg(xr + xb + u*d1 + iv); });
  cfor<d2>([&](auto J){ constexpr int jv = decltype(J)::value;
                        yv[jv] = __ldg(yr + yb + jv); });
  cfor<NA>([&](auto K){ acc[decltype(K)::value] = 0.0f; });

  cfor<d2>([&](auto J){
    cfor<d1>([&](auto I){
      constexpr int iv = decltype(I)::value, jv = decltype(J)::value;
      float pr = xv[iv]*yv[jv];   // shared across this task's l3 chunks
      cfor<C1-C0>([&](auto C){
        constexpr int cc = C0 + decltype(C)::value;
        constexpr int T  = GTT<SIDE, G, cc>;
        constexpr int p  = PTH<T>;
        constexpr int d3 = D3T<T>;
        constexpr int ao = ACCOFF<SIDE, G, cc> - A0;
        cfor<d3>([&](auto K){
          constexpr int kv = decltype(K)::value;
          constexpr float c = CW<p, iv, jv, kv>;
          if constexpr (c != 0.0f) acc[ao+kv] = fmaf(c, pr, acc[ao+kv]);  // FFMA-imm
        });
      });
    });
  });

  cfor<C1-C0>([&](auto C){
    constexpr int cc = C0 + decltype(C)::value;
    constexpr int T  = GTT<SIDE, G, cc>;
    constexpr int d3 = D3T<T>;
    constexpr int off= COFF<T> - HOFFV<SIDE>;   // side-local offset (compile-time)
    constexpr int ao = ACCOFF<SIDE, G, cc> - A0;
    cfor<d3>([&](auto K){ constexpr int kv = decltype(K)::value;
                          so[off + u*d3 + kv] = acc[ao+kv]; });      // odd stride -> conflict-free
  });
}

template<int SIDE, int W>
__device__ __forceinline__ void run_warp(int lane, float* __restrict__ so,
                                         const float* __restrict__ xr, const float* __restrict__ yr){
  cfor<MAXS>([&](auto S){
    constexpr int tk = SCHEDS[SIDE].t[W][decltype(S)::value];
    if constexpr (tk >= 0) do_group<SIDE,(tk>>1),(tk&1)>(lane, so, xr, yr);
  });
}

constexpr int ROWS = 8;   // batch rows per block (pipelined)

__global__ void __launch_bounds__(256, 6)
tp_kernel(const float* __restrict__ x, const float* __restrict__ y, float* __restrict__ out, int B){
  __shared__ __align__(16) float so[2][HMAX];   // half-row double buffer (~36 KB)

  const int base = blockIdx.x * ROWS;
  const int tid = threadIdx.x;
  const int w = tid >> 5, lane = tid & 31;

  int iter = 0;
  #pragma unroll 1
  for (int r = 0; r < ROWS; r++){
    const int b = base + r;
    if (b >= B) break;
    const float* xr = x + (long)b*576;
    const float* yr = y + (long)b*16;
    float* og = out + (long)b*9216;

    // ---------------- half 0 ----------------
    {
      float* sob = so[iter & 1];
      if (tid == 0 && iter >= 2)
        asm volatile("cp.async.bulk.wait_group.read 1;" ::: "memory");
      __syncthreads();
      switch (w){
        case 0: run_warp<0,0>(lane, sob, xr, yr); break;
        case 1: run_warp<0,1>(lane, sob, xr, yr); break;
        case 2: run_warp<0,2>(lane, sob, xr, yr); break;
        case 3: run_warp<0,3>(lane, sob, xr, yr); break;
        case 4: run_warp<0,4>(lane, sob, xr, yr); break;
        case 5: run_warp<0,5>(lane, sob, xr, yr); break;
        case 6: run_warp<0,6>(lane, sob, xr, yr); break;
        case 7: run_warp<0,7>(lane, sob, xr, yr); break;
      }
      asm volatile("fence.proxy.async.shared::cta;" ::: "memory");
      __syncthreads();
      if (tid == 0){
        unsigned sa = smem_u32(sob);
        asm volatile("cp.async.bulk.global.shared::cta.bulk_group [%0], [%1], %2;"
                     :: "l"(og + HOFF0), "r"(sa), "r"((unsigned)(HLEN0*4)) : "memory");
        asm volatile("cp.async.bulk.commit_group;" ::: "memory");
      }
      iter++;
    }

    // ---------------- half 1 ----------------
    {
      float* sob = so[iter & 1];
      if (tid == 0 && iter >= 2)
        asm volatile("cp.async.bulk.wait_group.read 1;" ::: "memory");
      __syncthreads();
      switch (w){
        case 0: run_warp<1,0>(lane, sob, xr, yr); break;
        case 1: run_warp<1,1>(lane, sob, xr, yr); break;
        case 2: run_warp<1,2>(lane, sob, xr, yr); break;
        case 3: run_warp<1,3>(lane, sob, xr, yr); break;
        case 4: run_warp<1,4>(lane, sob, xr, yr); break;
        case 5: run_warp<1,5>(lane, sob, xr, yr); break;
        case 6: run_warp<1,6>(lane, sob, xr, yr); break;
        case 7: run_warp<1,7>(lane, sob, xr, yr); break;
      }
      asm volatile("fence.proxy.async.shared::cta;" ::: "memory");
      __syncthreads();
      if (tid == 0){
        unsigned sa = smem_u32(sob);
        asm volatile("cp.async.bulk.global.shared::cta.bulk_group [%0], [%1], %2;"
                     :: "l"(og + HOFF1), "r"(sa), "r"((unsigned)(HLEN1*4)) : "memory");
        asm volatile("cp.async.bulk.commit_group;" ::: "memory");
      }
      iter++;
    }
  }

  // drain outstanding bulk stores before the CTA exits (smem dealloc)
  if (tid == 0)
    asm volatile("cp.async.bulk.wait_group.read 0;" ::: "memory");
  __syncthreads();
}

// ============================================================================
// Launch
// ============================================================================
extern "C" void kernel_launch(void* const* d_in, const int* in_sizes, int n_in,
                              void* d_out, int out_size) {
  const float* x = (const float*)d_in[0];
  const float* y = (const float*)d_in[1];
  float* out = (float*)d_out;
  const int B = in_sizes[0] / 576;
  if (B <= 0) return;
  const int blocks = (B + ROWS - 1) / ROWS;
  tp_kernel<<<blocks, 256>>>(x, y, out, B);
}